// round 2
// baseline (speedup 1.0000x reference)
#include <cuda_runtime.h>

#define NN 50000
#define EE 800000
#define FIN 128
#define HID 100
#define CL 16
#define LEAKYS 0.01f

// Scratch (alloc-free rule: __device__ globals). All fully rewritten each call.
__device__ float g_deg[NN];
__device__ float g_dinv[NN];
__device__ float g_Hs1[NN * HID];   // (x@W1) * dinv[row]
__device__ float g_out1[NN * HID];  // layer-1 aggregated output (pre-activation)
__device__ float g_Hs2[NN * CL];    // (leaky(out1)@W2) * dinv[row]

__device__ __forceinline__ void red_add_v4(float* p, float a, float b, float c, float d) {
    asm volatile("red.global.add.v4.f32 [%0], {%1,%2,%3,%4};"
                 :: "l"(p), "f"(a), "f"(b), "f"(c), "f"(d) : "memory");
}

__global__ void k_init_deg() {
    int i = blockIdx.x * blockDim.x + threadIdx.x;
    if (i < NN) g_deg[i] = 1.0f;  // self-loop
}

__global__ void k_deg(const int* __restrict__ ei) {
    int e = blockIdx.x * blockDim.x + threadIdx.x;
    if (e < EE) atomicAdd(&g_deg[ei[EE + e]], 1.0f);
}

__global__ void k_dinv() {
    int i = blockIdx.x * blockDim.x + threadIdx.x;
    if (i < NN) g_dinv[i] = rsqrtf(g_deg[i]);
}

// GEMM1: Hs1 = (x @ W1) * dinv ; out1 = b1 + Hs1 * dinv (self-loop term)
// BM=128, BN=128 (100 real cols, zero-padded), BK=16, 256 threads, 8x8 per thread.
__global__ __launch_bounds__(256) void k_gemm1(const float* __restrict__ x,
                                               const float* __restrict__ W1,
                                               const float* __restrict__ b1) {
    __shared__ float As[16][128];  // [k][m]
    __shared__ float Bs[16][128];  // [k][n]
    int tid = threadIdx.x;
    int tx = tid & 15, ty = tid >> 4;
    int m0 = blockIdx.x * 128;
    float acc[8][8];
#pragma unroll
    for (int i = 0; i < 8; i++)
#pragma unroll
        for (int j = 0; j < 8; j++) acc[i][j] = 0.0f;

    for (int kk = 0; kk < FIN; kk += 16) {
        // Load A tile (128 rows x 16 k), transposed into As[k][m]
#pragma unroll
        for (int q = 0; q < 2; q++) {
            int id = tid * 2 + q;
            int m = id >> 2, k4 = id & 3;
            int row = m0 + m;
            float4 v = make_float4(0.f, 0.f, 0.f, 0.f);
            if (row < NN) v = *(const float4*)(x + (long)row * FIN + kk + k4 * 4);
            As[k4 * 4 + 0][m] = v.x;
            As[k4 * 4 + 1][m] = v.y;
            As[k4 * 4 + 2][m] = v.z;
            As[k4 * 4 + 3][m] = v.w;
        }
        // Load B tile (16 k x 128 n), zero-pad n>=100
#pragma unroll
        for (int i = 0; i < 8; i++) {
            int idx = tid + i * 256;
            int k = idx >> 7, n = idx & 127;
            Bs[k][n] = (n < HID) ? W1[(kk + k) * HID + n] : 0.0f;
        }
        __syncthreads();
#pragma unroll
        for (int k = 0; k < 16; k++) {
            float a[8], b[8];
#pragma unroll
            for (int i = 0; i < 8; i++) a[i] = As[k][ty * 8 + i];
#pragma unroll
            for (int j = 0; j < 8; j++) b[j] = Bs[k][tx * 8 + j];
#pragma unroll
            for (int i = 0; i < 8; i++)
#pragma unroll
                for (int j = 0; j < 8; j++) acc[i][j] += a[i] * b[j];
        }
        __syncthreads();
    }
#pragma unroll
    for (int i = 0; i < 8; i++) {
        int row = m0 + ty * 8 + i;
        if (row >= NN) continue;
        float di = g_dinv[row];
#pragma unroll
        for (int j = 0; j < 8; j++) {
            int col = tx * 8 + j;
            if (col < HID) {
                float v = acc[i][j] * di;
                g_Hs1[(long)row * HID + col] = v;
                g_out1[(long)row * HID + col] = b1[col] + v * di;
            }
        }
    }
}

// Scatter layer 1: one warp per edge; lanes 0..24 each do one float4 vector-red.
__global__ void k_scatter1(const int* __restrict__ ei) {
    int w = (blockIdx.x * blockDim.x + threadIdx.x) >> 5;
    int lane = threadIdx.x & 31;
    if (w >= EE) return;
    int s = ei[w];
    int d = ei[EE + w];
    float nd = g_dinv[d];
    int c = lane * 4;
    if (c < HID) {
        float4 v = *(const float4*)(g_Hs1 + (long)s * HID + c);
        red_add_v4(g_out1 + (long)d * HID + c, v.x * nd, v.y * nd, v.z * nd, v.w * nd);
    }
}

// GEMM2: Hs2 = (leaky(out1) @ W2) * dinv ; d_out = b2 + Hs2*dinv (self-loop init)
__global__ __launch_bounds__(256) void k_gemm2(const float* __restrict__ W2,
                                               const float* __restrict__ b2,
                                               float* __restrict__ out) {
    __shared__ float W2s[HID][CL];
    __shared__ float b2s[CL];
    int tid = threadIdx.x;
    for (int i = tid; i < HID * CL; i += 256) W2s[i / CL][i % CL] = W2[i];
    if (tid < CL) b2s[tid] = b2[tid];
    __syncthreads();
    int row = blockIdx.x * 256 + tid;
    if (row >= NN) return;
    float acc[CL];
#pragma unroll
    for (int c = 0; c < CL; c++) acc[c] = 0.0f;
    const float4* h4 = (const float4*)(g_out1 + (long)row * HID);
#pragma unroll
    for (int k4 = 0; k4 < HID / 4; k4++) {
        float4 h = h4[k4];
        float hv[4] = {h.x, h.y, h.z, h.w};
#pragma unroll
        for (int r = 0; r < 4; r++) {
            float u = hv[r] > 0.0f ? hv[r] : LEAKYS * hv[r];
            int k = k4 * 4 + r;
#pragma unroll
            for (int c = 0; c < CL; c++) acc[c] += u * W2s[k][c];
        }
    }
    float di = g_dinv[row];
#pragma unroll
    for (int c = 0; c < CL; c++) {
        float v = acc[c] * di;
        g_Hs2[(long)row * CL + c] = v;
        out[(long)row * CL + c] = b2s[c] + v * di;
    }
}

// Scatter layer 2: 4 lanes per edge, each one float4 vector-red (16 floats/edge).
__global__ void k_scatter2(const int* __restrict__ ei, float* __restrict__ out) {
    int t = blockIdx.x * blockDim.x + threadIdx.x;
    int e = t >> 2, j = t & 3;
    if (e >= EE) return;
    int s = ei[e];
    int d = ei[EE + e];
    float nd = g_dinv[d];
    float4 v = *(const float4*)(g_Hs2 + (long)s * CL + j * 4);
    red_add_v4(out + (long)d * CL + j * 4, v.x * nd, v.y * nd, v.z * nd, v.w * nd);
}

// In-place log_softmax over 16 classes, one thread per row.
__global__ void k_lsm(float* __restrict__ out) {
    int row = blockIdx.x * blockDim.x + threadIdx.x;
    if (row >= NN) return;
    float4* p = (float4*)(out + (long)row * CL);
    float4 a = p[0], b = p[1], c = p[2], d = p[3];
    float v[CL] = {a.x, a.y, a.z, a.w, b.x, b.y, b.z, b.w,
                   c.x, c.y, c.z, c.w, d.x, d.y, d.z, d.w};
    float m = v[0];
#pragma unroll
    for (int i = 1; i < CL; i++) m = fmaxf(m, v[i]);
    float s = 0.0f;
#pragma unroll
    for (int i = 0; i < CL; i++) s += expf(v[i] - m);
    float l = m + logf(s);
#pragma unroll
    for (int i = 0; i < CL; i++) v[i] -= l;
    p[0] = make_float4(v[0], v[1], v[2], v[3]);
    p[1] = make_float4(v[4], v[5], v[6], v[7]);
    p[2] = make_float4(v[8], v[9], v[10], v[11]);
    p[3] = make_float4(v[12], v[13], v[14], v[15]);
}

extern "C" void kernel_launch(void* const* d_in, const int* in_sizes, int n_in,
                              void* d_out, int out_size) {
    const float* x  = (const float*)d_in[0];
    const float* W1 = (const float*)d_in[1];
    const float* b1 = (const float*)d_in[2];
    const float* W2 = (const float*)d_in[3];
    const float* b2 = (const float*)d_in[4];
    const int*   ei = (const int*)d_in[5];
    float* out = (float*)d_out;

    k_init_deg<<<(NN + 255) / 256, 256>>>();
    k_deg<<<(EE + 255) / 256, 256>>>(ei);
    k_dinv<<<(NN + 255) / 256, 256>>>();
    k_gemm1<<<(NN + 127) / 128, 256>>>(x, W1, b1);
    k_scatter1<<<(EE + 7) / 8, 256>>>(ei);
    k_gemm2<<<(NN + 255) / 256, 256>>>(W2, b2, out);
    k_scatter2<<<((long)EE * 4 + 255) / 256, 256>>>(ei, out);
    k_lsm<<<(NN + 255) / 256, 256>>>(out);
}

// round 3
// speedup vs baseline: 1.0379x; 1.0379x over previous
#include <cuda_runtime.h>

#define NN 50000
#define EE 800000
#define FIN 128
#define HID 100
#define CL 16
#define LEAKYS 0.01f

// Scratch (alloc-free rule: __device__ globals). All fully rewritten each call.
__device__ float g_deg[NN];
__device__ float g_dinv[NN];
__device__ float g_Hs1[NN * HID];   // (x@W1) * dinv[row]
__device__ float g_out1[NN * HID];  // layer-1 aggregated output (pre-activation)
__device__ float g_Hs2[NN * CL];    // (leaky(out1)@W2) * dinv[row]

__device__ __forceinline__ void red_add_v4(float* p, float a, float b, float c, float d) {
    asm volatile("red.global.add.v4.f32 [%0], {%1,%2,%3,%4};"
                 :: "l"(p), "f"(a), "f"(b), "f"(c), "f"(d) : "memory");
}

__global__ void k_init_deg() {
    int i = blockIdx.x * blockDim.x + threadIdx.x;
    if (i < NN) g_deg[i] = 1.0f;  // self-loop
}

__global__ void k_deg(const int* __restrict__ ei) {
    int e = blockIdx.x * blockDim.x + threadIdx.x;
    if (e < EE) atomicAdd(&g_deg[ei[EE + e]], 1.0f);
}

__global__ void k_dinv() {
    int i = blockIdx.x * blockDim.x + threadIdx.x;
    if (i < NN) g_dinv[i] = rsqrtf(g_deg[i]);
}

// GEMM1: Hs1 = (x @ W1) * dinv ; out1 = b1 + Hs1 * dinv (self-loop term)
// BM=128, BN=128 (100 real cols zero-padded), BK=16, 256 threads, 8x8/thread.
// Double-buffered smem, software-pipelined global loads, LDS.128 fragments.
__global__ __launch_bounds__(256) void k_gemm1(const float* __restrict__ x,
                                               const float* __restrict__ W1,
                                               const float* __restrict__ b1) {
    __shared__ float As[2][16][128];  // [buf][k][m]
    __shared__ float Bs[2][16][128];  // [buf][k][n]
    int tid = threadIdx.x;
    int tx = tid & 15, ty = tid >> 4;
    int m0 = blockIdx.x * 128;

    // A staging: thread loads 8 floats of row (m0 + tid>>1), k-offset (tid&1)*8
    int mA = tid >> 1;
    int kA = (tid & 1) * 8;
    int rowA = m0 + mA;
    bool okA = rowA < NN;
    const float* xrow = x + (long)rowA * FIN + kA;

    float4 rA0, rA1;
    float rB[8];

    // ---- prologue: tile 0 ----
    {
        rA0 = okA ? *(const float4*)(xrow + 0) : make_float4(0, 0, 0, 0);
        rA1 = okA ? *(const float4*)(xrow + 4) : make_float4(0, 0, 0, 0);
#pragma unroll
        for (int i = 0; i < 8; i++) {
            int idx = tid + i * 256;
            int k = idx >> 7, n = idx & 127;
            rB[i] = (n < HID) ? W1[k * HID + n] : 0.0f;
        }
        float av[8] = {rA0.x, rA0.y, rA0.z, rA0.w, rA1.x, rA1.y, rA1.z, rA1.w};
#pragma unroll
        for (int j = 0; j < 8; j++) As[0][kA + j][mA] = av[j];
#pragma unroll
        for (int i = 0; i < 8; i++) {
            int idx = tid + i * 256;
            Bs[0][idx >> 7][idx & 127] = rB[i];
        }
    }
    __syncthreads();

    float acc[8][8];
#pragma unroll
    for (int i = 0; i < 8; i++)
#pragma unroll
        for (int j = 0; j < 8; j++) acc[i][j] = 0.0f;

    for (int t = 0; t < 8; t++) {
        int buf = t & 1;
        if (t < 7) {
            int kk = (t + 1) * 16;
            rA0 = okA ? *(const float4*)(xrow + kk + 0) : make_float4(0, 0, 0, 0);
            rA1 = okA ? *(const float4*)(xrow + kk + 4) : make_float4(0, 0, 0, 0);
#pragma unroll
            for (int i = 0; i < 8; i++) {
                int idx = tid + i * 256;
                int k = idx >> 7, n = idx & 127;
                rB[i] = (n < HID) ? W1[(kk + k) * HID + n] : 0.0f;
            }
        }
#pragma unroll
        for (int k = 0; k < 16; k++) {
            float4 a0 = *(const float4*)&As[buf][k][ty * 8];
            float4 a1 = *(const float4*)&As[buf][k][ty * 8 + 4];
            float4 b0 = *(const float4*)&Bs[buf][k][tx * 8];
            float4 b1v = *(const float4*)&Bs[buf][k][tx * 8 + 4];
            float a[8] = {a0.x, a0.y, a0.z, a0.w, a1.x, a1.y, a1.z, a1.w};
            float b[8] = {b0.x, b0.y, b0.z, b0.w, b1v.x, b1v.y, b1v.z, b1v.w};
#pragma unroll
            for (int i = 0; i < 8; i++)
#pragma unroll
                for (int j = 0; j < 8; j++) acc[i][j] += a[i] * b[j];
        }
        if (t < 7) {
            int nb = buf ^ 1;
            float av[8] = {rA0.x, rA0.y, rA0.z, rA0.w, rA1.x, rA1.y, rA1.z, rA1.w};
#pragma unroll
            for (int j = 0; j < 8; j++) As[nb][kA + j][mA] = av[j];
#pragma unroll
            for (int i = 0; i < 8; i++) {
                int idx = tid + i * 256;
                Bs[nb][idx >> 7][idx & 127] = rB[i];
            }
            __syncthreads();
        }
    }

#pragma unroll
    for (int i = 0; i < 8; i++) {
        int row = m0 + ty * 8 + i;
        if (row >= NN) continue;
        float di = g_dinv[row];
#pragma unroll
        for (int j = 0; j < 8; j++) {
            int col = tx * 8 + j;
            if (col < HID) {
                float v = acc[i][j] * di;
                g_Hs1[(long)row * HID + col] = v;
                g_out1[(long)row * HID + col] = b1[col] + v * di;
            }
        }
    }
}

// Scatter layer 1: flat thread per (edge, float4) — 25 float4 per edge, 100% lanes.
__global__ void k_scatter1(const int* __restrict__ ei) {
    int t = blockIdx.x * blockDim.x + threadIdx.x;
    if (t >= EE * 25) return;
    int e = t / 25;
    int j = t - e * 25;
    int s = ei[e];
    int d = ei[EE + e];
    float nd = g_dinv[d];
    float4 v = *(const float4*)(g_Hs1 + (long)s * HID + j * 4);
    red_add_v4(g_out1 + (long)d * HID + j * 4, v.x * nd, v.y * nd, v.z * nd, v.w * nd);
}

// GEMM2: Hs2 = (leaky(out1) @ W2) * dinv ; d_out = b2 + Hs2*dinv (self-loop init)
__global__ __launch_bounds__(256) void k_gemm2(const float* __restrict__ W2,
                                               const float* __restrict__ b2,
                                               float* __restrict__ out) {
    __shared__ float W2s[HID][CL];
    __shared__ float b2s[CL];
    int tid = threadIdx.x;
    for (int i = tid; i < HID * CL; i += 256) W2s[i / CL][i % CL] = W2[i];
    if (tid < CL) b2s[tid] = b2[tid];
    __syncthreads();
    int row = blockIdx.x * 256 + tid;
    if (row >= NN) return;
    float acc[CL];
#pragma unroll
    for (int c = 0; c < CL; c++) acc[c] = 0.0f;
    const float4* h4 = (const float4*)(g_out1 + (long)row * HID);
#pragma unroll
    for (int k4 = 0; k4 < HID / 4; k4++) {
        float4 h = h4[k4];
        float hv[4] = {h.x, h.y, h.z, h.w};
#pragma unroll
        for (int r = 0; r < 4; r++) {
            float u = hv[r] > 0.0f ? hv[r] : LEAKYS * hv[r];
            int k = k4 * 4 + r;
#pragma unroll
            for (int c = 0; c < CL; c++) acc[c] += u * W2s[k][c];
        }
    }
    float di = g_dinv[row];
#pragma unroll
    for (int c = 0; c < CL; c++) {
        float v = acc[c] * di;
        g_Hs2[(long)row * CL + c] = v;
        out[(long)row * CL + c] = b2s[c] + v * di;
    }
}

// Scatter layer 2: 4 lanes per edge, each one float4 vector-red (16 floats/edge).
__global__ void k_scatter2(const int* __restrict__ ei, float* __restrict__ out) {
    int t = blockIdx.x * blockDim.x + threadIdx.x;
    int e = t >> 2, j = t & 3;
    if (e >= EE) return;
    int s = ei[e];
    int d = ei[EE + e];
    float nd = g_dinv[d];
    float4 v = *(const float4*)(g_Hs2 + (long)s * CL + j * 4);
    red_add_v4(out + (long)d * CL + j * 4, v.x * nd, v.y * nd, v.z * nd, v.w * nd);
}

// In-place log_softmax over 16 classes, one thread per row.
__global__ void k_lsm(float* __restrict__ out) {
    int row = blockIdx.x * blockDim.x + threadIdx.x;
    if (row >= NN) return;
    float4* p = (float4*)(out + (long)row * CL);
    float4 a = p[0], b = p[1], c = p[2], d = p[3];
    float v[CL] = {a.x, a.y, a.z, a.w, b.x, b.y, b.z, b.w,
                   c.x, c.y, c.z, c.w, d.x, d.y, d.z, d.w};
    float m = v[0];
#pragma unroll
    for (int i = 1; i < CL; i++) m = fmaxf(m, v[i]);
    float s = 0.0f;
#pragma unroll
    for (int i = 0; i < CL; i++) s += expf(v[i] - m);
    float l = m + logf(s);
#pragma unroll
    for (int i = 0; i < CL; i++) v[i] -= l;
    p[0] = make_float4(v[0], v[1], v[2], v[3]);
    p[1] = make_float4(v[4], v[5], v[6], v[7]);
    p[2] = make_float4(v[8], v[9], v[10], v[11]);
    p[3] = make_float4(v[12], v[13], v[14], v[15]);
}

extern "C" void kernel_launch(void* const* d_in, const int* in_sizes, int n_in,
                              void* d_out, int out_size) {
    const float* x  = (const float*)d_in[0];
    const float* W1 = (const float*)d_in[1];
    const float* b1 = (const float*)d_in[2];
    const float* W2 = (const float*)d_in[3];
    const float* b2 = (const float*)d_in[4];
    const int*   ei = (const int*)d_in[5];
    float* out = (float*)d_out;

    k_init_deg<<<(NN + 255) / 256, 256>>>();
    k_deg<<<(EE + 255) / 256, 256>>>(ei);
    k_dinv<<<(NN + 255) / 256, 256>>>();
    k_gemm1<<<(NN + 127) / 128, 256>>>(x, W1, b1);
    k_scatter1<<<(EE * 25 + 255) / 256, 256>>>(ei);
    k_gemm2<<<(NN + 255) / 256, 256>>>(W2, b2, out);
    k_scatter2<<<(EE * 4 + 255) / 256, 256>>>(ei, out);
    k_lsm<<<(NN + 255) / 256, 256>>>(out);
}

// round 4
// speedup vs baseline: 1.3049x; 1.2572x over previous
#include <cuda_runtime.h>

#define NN 50000
#define EE 800000
#define FIN 128
#define HID 100
#define CL 16
#define LEAKYS 0.01f
#define NB_SCAN 196   // ceil(NN/256)

// Scratch (alloc-free rule: __device__ globals). All fully rewritten each call.
__device__ int   g_cnt[NN];
__device__ int   g_off[NN];
__device__ int   g_cur[NN];
__device__ int   g_bsum[256];
__device__ float g_dinv[NN];
__device__ int   g_csrc[EE];
__device__ float g_Hs1[NN * HID];  // (x@W1) * dinv[row]
__device__ float g_Hs2[NN * CL];   // (leaky(out1)@W2) * dinv[row]

__global__ void k_zero() {
    int i = blockIdx.x * blockDim.x + threadIdx.x;
    if (i < NN) g_cnt[i] = 0;
}

__global__ void k_hist(const int* __restrict__ ei) {
    int e = blockIdx.x * blockDim.x + threadIdx.x;
    if (e < EE) atomicAdd(&g_cnt[ei[EE + e]], 1);
}

// Per-block exclusive scan of counts; also dinv = rsqrt(cnt+1).
__global__ void k_scanA() {
    __shared__ int s[256];
    int tid = threadIdx.x;
    int i = blockIdx.x * 256 + tid;
    int val = (i < NN) ? g_cnt[i] : 0;
    if (i < NN) g_dinv[i] = rsqrtf((float)val + 1.0f);
    s[tid] = val;
    __syncthreads();
#pragma unroll
    for (int off = 1; off < 256; off <<= 1) {
        int t = (tid >= off) ? s[tid - off] : 0;
        __syncthreads();
        s[tid] += t;
        __syncthreads();
    }
    if (i < NN) g_off[i] = s[tid] - val;        // local exclusive
    if (tid == 255) g_bsum[blockIdx.x] = s[255]; // block total
}

__global__ void k_scanB() {
    __shared__ int s[256];
    int tid = threadIdx.x;
    int val = (tid < NB_SCAN) ? g_bsum[tid] : 0;
    s[tid] = val;
    __syncthreads();
#pragma unroll
    for (int off = 1; off < 256; off <<= 1) {
        int t = (tid >= off) ? s[tid - off] : 0;
        __syncthreads();
        s[tid] += t;
        __syncthreads();
    }
    g_bsum[tid] = s[tid] - val;  // exclusive
}

__global__ void k_scanC() {
    int i = blockIdx.x * 256 + threadIdx.x;
    if (i < NN) {
        int o = g_off[i] + g_bsum[blockIdx.x];
        g_off[i] = o;
        g_cur[i] = o;
    }
}

__global__ void k_place(const int* __restrict__ ei) {
    int e = blockIdx.x * blockDim.x + threadIdx.x;
    if (e < EE) {
        int d = ei[EE + e];
        int pos = atomicAdd(&g_cur[d], 1);
        g_csrc[pos] = ei[e];
    }
}

// GEMM1: Hs1 = (x @ W1) * dinv[row]. BM=128,BN=128(pad),BK=16, 8x8/thread.
__global__ __launch_bounds__(256) void k_gemm1(const float* __restrict__ x,
                                               const float* __restrict__ W1) {
    __shared__ float As[2][16][128];
    __shared__ float Bs[2][16][128];
    int tid = threadIdx.x;
    int tx = tid & 15, ty = tid >> 4;
    int m0 = blockIdx.x * 128;

    int mA = tid >> 1;
    int kA = (tid & 1) * 8;
    int rowA = m0 + mA;
    bool okA = rowA < NN;
    const float* xrow = x + (long)rowA * FIN + kA;

    float4 rA0, rA1;
    float rB[8];
    {
        rA0 = okA ? *(const float4*)(xrow + 0) : make_float4(0, 0, 0, 0);
        rA1 = okA ? *(const float4*)(xrow + 4) : make_float4(0, 0, 0, 0);
#pragma unroll
        for (int i = 0; i < 8; i++) {
            int idx = tid + i * 256;
            int k = idx >> 7, n = idx & 127;
            rB[i] = (n < HID) ? W1[k * HID + n] : 0.0f;
        }
        float av[8] = {rA0.x, rA0.y, rA0.z, rA0.w, rA1.x, rA1.y, rA1.z, rA1.w};
#pragma unroll
        for (int j = 0; j < 8; j++) As[0][kA + j][mA] = av[j];
#pragma unroll
        for (int i = 0; i < 8; i++) {
            int idx = tid + i * 256;
            Bs[0][idx >> 7][idx & 127] = rB[i];
        }
    }
    __syncthreads();

    float acc[8][8];
#pragma unroll
    for (int i = 0; i < 8; i++)
#pragma unroll
        for (int j = 0; j < 8; j++) acc[i][j] = 0.0f;

    for (int t = 0; t < 8; t++) {
        int buf = t & 1;
        if (t < 7) {
            int kk = (t + 1) * 16;
            rA0 = okA ? *(const float4*)(xrow + kk + 0) : make_float4(0, 0, 0, 0);
            rA1 = okA ? *(const float4*)(xrow + kk + 4) : make_float4(0, 0, 0, 0);
#pragma unroll
            for (int i = 0; i < 8; i++) {
                int idx = tid + i * 256;
                int k = idx >> 7, n = idx & 127;
                rB[i] = (n < HID) ? W1[(kk + k) * HID + n] : 0.0f;
            }
        }
#pragma unroll
        for (int k = 0; k < 16; k++) {
            float4 a0 = *(const float4*)&As[buf][k][ty * 8];
            float4 a1 = *(const float4*)&As[buf][k][ty * 8 + 4];
            float4 b0 = *(const float4*)&Bs[buf][k][tx * 8];
            float4 b1v = *(const float4*)&Bs[buf][k][tx * 8 + 4];
            float a[8] = {a0.x, a0.y, a0.z, a0.w, a1.x, a1.y, a1.z, a1.w};
            float b[8] = {b0.x, b0.y, b0.z, b0.w, b1v.x, b1v.y, b1v.z, b1v.w};
#pragma unroll
            for (int i = 0; i < 8; i++)
#pragma unroll
                for (int j = 0; j < 8; j++) acc[i][j] += a[i] * b[j];
        }
        if (t < 7) {
            int nb = buf ^ 1;
            float av[8] = {rA0.x, rA0.y, rA0.z, rA0.w, rA1.x, rA1.y, rA1.z, rA1.w};
#pragma unroll
            for (int j = 0; j < 8; j++) As[nb][kA + j][mA] = av[j];
#pragma unroll
            for (int i = 0; i < 8; i++) {
                int idx = tid + i * 256;
                Bs[nb][idx >> 7][idx & 127] = rB[i];
            }
            __syncthreads();
        }
    }

#pragma unroll
    for (int i = 0; i < 8; i++) {
        int row = m0 + ty * 8 + i;
        if (row >= NN) continue;
        float di = g_dinv[row];
#pragma unroll
        for (int j = 0; j < 8; j++) {
            int col = tx * 8 + j;
            if (col < HID) g_Hs1[(long)row * HID + col] = acc[i][j] * di;
        }
    }
}

// Gather layer 1 + leaky + fused GEMM2 epilogue.
// One warp per dst node. Lane owns cols {lane, lane+32, lane+64, lane+96<100}.
// acc = Hs1[d] + sum_{s in N(d)} Hs1[s];  out1 = b1 + dinv[d]*acc; u = leaky(out1)
// Then: Hs2[d][c] = dinv[d] * sum_k u[k]*W2[k][c];  out[d][c] = b2[c] + Hs2[d][c]*dinv[d]
__global__ __launch_bounds__(256) void k_gather1(const float* __restrict__ b1,
                                                 const float* __restrict__ W2,
                                                 const float* __restrict__ b2,
                                                 float* __restrict__ out) {
    __shared__ float W2s[HID][17];  // padded to dodge bank conflicts
    __shared__ float b1s[HID];
    __shared__ float b2s[CL];
    __shared__ float us[8][HID];    // per-warp activated row
    int tid = threadIdx.x;
    for (int i = tid; i < HID * CL; i += 256) W2s[i / CL][i % CL] = W2[i];
    for (int i = tid; i < HID; i += 256) b1s[i] = b1[i];
    if (tid < CL) b2s[tid] = b2[tid];
    __syncthreads();

    int wid = tid >> 5, lane = tid & 31;
    int node = blockIdx.x * 8 + wid;
    if (node >= NN) return;

    int c0 = lane, c1 = lane + 32, c2 = lane + 64, c3 = lane + 96;
    bool has3 = c3 < HID;
    const float* selfrow = g_Hs1 + (long)node * HID;
    float a0 = selfrow[c0];
    float a1 = selfrow[c1];
    float a2 = selfrow[c2];
    float a3 = has3 ? selfrow[c3] : 0.0f;

    int start = g_off[node];
    int end = start + g_cnt[node];
    for (int j = start; j < end; j++) {
        int s = g_csrc[j];
        const float* r = g_Hs1 + (long)s * HID;
        a0 += r[c0];
        a1 += r[c1];
        a2 += r[c2];
        if (has3) a3 += r[c3];
    }

    float di = g_dinv[node];
    float o0 = b1s[c0] + di * a0;
    float o1 = b1s[c1] + di * a1;
    float o2 = b1s[c2] + di * a2;
    us[wid][c0] = o0 > 0.f ? o0 : LEAKYS * o0;
    us[wid][c1] = o1 > 0.f ? o1 : LEAKYS * o1;
    us[wid][c2] = o2 > 0.f ? o2 : LEAKYS * o2;
    if (has3) {
        float o3 = b1s[c3] + di * a3;
        us[wid][c3] = o3 > 0.f ? o3 : LEAKYS * o3;
    }
    __syncwarp();

    // Fused GEMM2: lane (c = lane&15, half = lane>>4) sums 50 k's.
    int c = lane & 15;
    int k0 = (lane >> 4) * 50;
    float p = 0.0f;
#pragma unroll 5
    for (int k = 0; k < 50; k++) {
        p += us[wid][k0 + k] * W2s[k0 + k][c];
    }
    p += __shfl_xor_sync(0xffffffffu, p, 16);
    if (lane < 16) {
        float h2 = di * p;
        g_Hs2[(long)node * CL + c] = h2;
        out[(long)node * CL + c] = b2s[c] + h2 * di;
    }
}

// Gather layer 2 + log_softmax. 16 lanes per node.
__global__ __launch_bounds__(256) void k_gather2(float* __restrict__ out) {
    int t = blockIdx.x * 256 + threadIdx.x;
    int node = t >> 4;
    int c = t & 15;
    if (node >= NN) return;

    int start = g_off[node];
    int end = start + g_cnt[node];
    float acc = 0.0f;
    for (int j = start; j < end; j++) {
        int s = g_csrc[j];
        acc += g_Hs2[(long)s * CL + c];
    }
    float v = out[(long)node * CL + c] + g_dinv[node] * acc;

    // log_softmax across the 16 lanes of this node
    float m = v;
#pragma unroll
    for (int msk = 8; msk >= 1; msk >>= 1)
        m = fmaxf(m, __shfl_xor_sync(0xffffffffu, m, msk, 16));
    float e = expf(v - m);
#pragma unroll
    for (int msk = 8; msk >= 1; msk >>= 1)
        e += __shfl_xor_sync(0xffffffffu, e, msk, 16);
    out[(long)node * CL + c] = v - m - logf(e);
}

extern "C" void kernel_launch(void* const* d_in, const int* in_sizes, int n_in,
                              void* d_out, int out_size) {
    const float* x  = (const float*)d_in[0];
    const float* W1 = (const float*)d_in[1];
    const float* b1 = (const float*)d_in[2];
    const float* W2 = (const float*)d_in[3];
    const float* b2 = (const float*)d_in[4];
    const int*   ei = (const int*)d_in[5];
    float* out = (float*)d_out;

    k_zero<<<NB_SCAN, 256>>>();
    k_hist<<<(EE + 255) / 256, 256>>>(ei);
    k_scanA<<<NB_SCAN, 256>>>();
    k_scanB<<<1, 256>>>();
    k_scanC<<<NB_SCAN, 256>>>();
    k_place<<<(EE + 255) / 256, 256>>>(ei);
    k_gemm1<<<(NN + 127) / 128, 256>>>(x, W1);
    k_gather1<<<(NN + 7) / 8, 256>>>(b1, W2, b2, out);
    k_gather2<<<(NN * 16 + 255) / 256, 256>>>(out);
}